// round 5
// baseline (speedup 1.0000x reference)
#include <cuda_runtime.h>
#include <cstdint>

// ---------------------------------------------------------------------------
// LSTM Neural Hawkes Process NLL  (B=64, L=1024, H=64)
// R5: TWO-BATCH SOFTWARE PIPELINE. 32 CTAs x 448 threads. While epilogue
// warps (12,13) process batch A's step, producer warps (0-11) compute batch
// B's GEMM. 4 named barriers, arrive/sync role-split: nobody blocks on work
// they themselves produce. Critical path ~= producer GEMM issue only.
// ---------------------------------------------------------------------------

#define BATCH   64
#define MAXL    1024
#define LP1     1025
#define HID     64
#define SEVENH  448
#define NMC     30
#define T_END   100.0f
#define EPS_L   1e-10f
#define TOTAL   (BATCH * LP1)          // 65600
#define LOG2E   1.4426950408889634f
#define LN2     0.6931471805599453f

// ------------------------- device scratch (no mallocs) ---------------------
__device__ float4 g_state [TOTAL * HID];   // {c, cbar, o, dec}
__device__ float  g_before[TOTAL * HID];
__device__ float  g_dt    [TOTAL];
__device__ float  g_part  [TOTAL];

// ------------------------------ fast math -----------------------------------
__device__ __forceinline__ float ex2f(float x){ float y; asm("ex2.approx.f32 %0,%1;":"=f"(y):"f"(x)); return y; }
__device__ __forceinline__ float lg2f(float x){ float y; asm("lg2.approx.f32 %0,%1;":"=f"(y):"f"(x)); return y; }
__device__ __forceinline__ float tanh_mufu(float x){ float y; asm("tanh.approx.f32 %0,%1;":"=f"(y):"f"(x)); return y; }
__device__ __forceinline__ float fsig(float x){ return fmaf(0.5f, tanh_mufu(0.5f * x), 0.5f); }
__device__ __forceinline__ float fsoftplus(float x){
    return fmaxf(x, 0.0f) + LN2 * lg2f(1.0f + ex2f(-fabsf(x) * LOG2E));
}
__device__ __forceinline__ float flog(float x){ return LN2 * lg2f(x); }

// ------------------------------ packed f32x2 --------------------------------
__device__ __forceinline__ void fma2(unsigned long long& d, unsigned long long a, unsigned long long b){
    asm("fma.rn.f32x2 %0, %1, %2, %0;" : "+l"(d) : "l"(a), "l"(b));
}
__device__ __forceinline__ void add2(unsigned long long& d, unsigned long long a){
    asm("add.rn.f32x2 %0, %1, %0;" : "+l"(d) : "l"(a));
}
__device__ __forceinline__ unsigned long long pack2(float lo, float hi){
    unsigned long long r; asm("mov.b64 %0, {%1,%2};" : "=l"(r) : "f"(lo), "f"(hi)); return r;
}
__device__ __forceinline__ float2 unpack2(unsigned long long v){
    float2 r; asm("mov.b64 {%0,%1}, %2;" : "=f"(r.x), "=f"(r.y) : "l"(v)); return r;
}

// ------------------------------ named barriers ------------------------------
#define BAR_SYNC(id)   asm volatile("bar.sync %0, %1;"   :: "r"(id), "r"(SEVENH) : "memory")
#define BAR_ARRIVE(id) asm volatile("bar.arrive %0, %1;" :: "r"(id), "r"(SEVENH) : "memory")

// ------------------------------ Threefry-2x32-20 ----------------------------
__device__ __forceinline__ uint32_t rotl32(uint32_t x, int r){ return (x << r) | (x >> (32 - r)); }
__device__ __forceinline__ float tf_uniform(uint32_t flat){
    // JAX partitionable threefry, key (0,42): bits = out0 ^ out1
    uint32_t k0 = 0u, k1 = 42u, ks2 = k0 ^ k1 ^ 0x1BD11BDAu;
    uint32_t x0 = 0u + k0, x1 = flat + k1;
#define TF_R(r) { x0 += x1; x1 = rotl32(x1, (r)); x1 ^= x0; }
    TF_R(13) TF_R(15) TF_R(26) TF_R(6)   x0 += k1;  x1 += ks2 + 1u;
    TF_R(17) TF_R(29) TF_R(16) TF_R(24)  x0 += ks2; x1 += k0  + 2u;
    TF_R(13) TF_R(15) TF_R(26) TF_R(6)   x0 += k0;  x1 += k1  + 3u;
    TF_R(17) TF_R(29) TF_R(16) TF_R(24)  x0 += k1;  x1 += ks2 + 4u;
    TF_R(13) TF_R(15) TF_R(26) TF_R(6)   x0 += ks2; x1 += k0  + 5u;
#undef TF_R
    uint32_t bits = x0 ^ x1;
    return __uint_as_float((bits >> 9) | 0x3F800000u) - 1.0f;
}

// one 65-long packed-f32x2 column dot against shared h
__device__ __forceinline__ float col_dot(const float* sh, const unsigned long long* w2,
                                         float w0, float bj, float dt)
{
    unsigned long long a0 = 0ull, a1 = 0ull, a2 = 0ull, a3 = 0ull;
    const ulonglong2* h2 = reinterpret_cast<const ulonglong2*>(sh);
#pragma unroll
    for (int q = 0; q < 4; q++) {
        ulonglong2 u = h2[2*q], v = h2[2*q + 1];
        fma2(a0, w2[4*q + 0],  u.x);
        fma2(a1, w2[4*q + 1],  u.y);
        fma2(a2, w2[4*q + 2],  v.x);
        fma2(a3, w2[4*q + 3],  v.y);
        ulonglong2 s = h2[2*q + 8], t = h2[2*q + 9];
        fma2(a0, w2[4*q + 16], s.x);
        fma2(a1, w2[4*q + 17], s.y);
        fma2(a2, w2[4*q + 18], t.x);
        fma2(a3, w2[4*q + 19], t.y);
    }
    add2(a0, a1); add2(a2, a3); add2(a0, a2);
    float2 r = unpack2(a0);
    return (r.x + r.y) + fmaf(w0, dt, bj);
}

// ------------------------------ Kernel 1: scan -------------------------------
// One CTA per TWO batches. Producers (warps 0-11) stream GEMM-A, GEMM-B
// back-to-back each iteration; epilogue warps (12,13 = the gate-6 columns)
// run EPI-A during GEMM-B and EPI-B during the next GEMM-A.
__global__ void __launch_bounds__(SEVENH, 1)
scan_kernel(const float* __restrict__ seq,    // [B, L, 1]
            const float* __restrict__ Wrec,   // [65, 448]
            const float* __restrict__ brec,   // [448]
            const int*   __restrict__ lens)   // [B]
{
    __shared__ __align__(16) float s_h[2][HID];
    __shared__ float s_v[2][SEVENH];
    __shared__ float s_dt[2][LP1];

    const int bA = blockIdx.x * 2;
    const int bB = bA + 1;
    const int j  = threadIdx.x;
    const int lenA = lens[bA];
    const int lenB = lens[bB];
    const int lmax = max(lenA, lenB);
    const float* spA = seq + bA * MAXL;
    const float* spB = seq + bB * MAXL;

    for (int l = j; l <= MAXL; l += SEVENH) {
        float vA, vB;
        if (l < lenA)        vA = (l == 0) ? spA[0] : spA[l] - spA[l - 1];
        else if (l == lenA)  vA = T_END - spA[lenA - 1];
        else                 vA = -1.0f;
        if (l < lenB)        vB = (l == 0) ? spB[0] : spB[l] - spB[l - 1];
        else if (l == lenB)  vB = T_END - spB[lenB - 1];
        else                 vB = -1.0f;
        s_dt[0][l] = vA;  g_dt[bA * LP1 + l] = vA;
        s_dt[1][l] = vB;  g_dt[bB * LP1 + l] = vB;
    }

    if (j >= 384) {                     // epilogue threads init state index 0
        const int ch = j - 384;
        s_h[0][ch] = 0.0f; s_h[1][ch] = 0.0f;
        g_state [(bA * LP1) * HID + ch] = make_float4(0.f, 0.f, 0.f, 0.f);
        g_state [(bB * LP1) * HID + ch] = make_float4(0.f, 0.f, 0.f, 0.f);
        g_before[(bA * LP1) * HID + ch] = 0.0f;
        g_before[(bB * LP1) * HID + ch] = 0.0f;
    }

    // column weights (shared across both batches): row 0 scalar + 32 f32x2
    const float w0 = Wrec[j];
    const float bj = brec[j];
    unsigned long long w2[32];
#pragma unroll
    for (int k = 0; k < 32; k++)
        w2[k] = pack2(Wrec[(2*k + 1) * SEVENH + j], Wrec[(2*k + 2) * SEVENH + j]);

    __syncthreads();

    if (j < 384) {
        // ---------------- producers: warps 0-11 (gates 0..5) ----------------
        const int gate = j >> 6;        // 0:i 1:f 2:z 3:o 4:ib 5:fb
        for (int l = 0; l < lmax; l++) {
            float accA = col_dot(s_h[0], w2, w0, bj, s_dt[0][l]);
            s_v[0][j] = (gate == 2) ? tanh_mufu(accA) : fsig(accA);
            BAR_ARRIVE(1);              // gates A published

            float accB = col_dot(s_h[1], w2, w0, bj, s_dt[1][l]);
            s_v[1][j] = (gate == 2) ? tanh_mufu(accB) : fsig(accB);
            BAR_ARRIVE(3);              // gates B published

            BAR_SYNC(2);                // h_A(l+1) ready (EPI-A done)
            BAR_SYNC(4);                // h_B(l+1) ready (EPI-B done)
        }
    } else {
        // ------------- epilogue: warps 12,13 (= gate-6 columns) -------------
        const int ch = j - 384;
        float ctA = 0.0f, cbA = 0.0f, ctB = 0.0f, cbB = 0.0f;
        for (int l = 0; l < lmax; l++) {
            const bool aA = l < lenA;
            const bool aB = l < lenB;

            // own GEMM-A column -> decay + exp factor (overlaps producer GEMM-A)
            const float accA = col_dot(s_h[0], w2, w0, bj, s_dt[0][l]);
            const float decA = fsoftplus(accA);
            const float eA   = ex2f(-decA * s_dt[0][l + 1] * LOG2E);

            BAR_SYNC(1);                // wait gates A
            float cA = 0.f, cbnA = 0.f, oA = 0.f, befA = 0.f;
            if (aA) {
                const float iG = s_v[0][ch],        fG = s_v[0][ 64 + ch];
                const float zG = s_v[0][128 + ch],  oG = s_v[0][192 + ch];
                const float ib = s_v[0][256 + ch],  fb = s_v[0][320 + ch];
                cA   = fmaf(fG, ctA, iG * zG);
                cbnA = fmaf(fb, cbA, ib * zG);
                const float cd = fmaf(cA - cbnA, eA, cbnA);
                befA = oG * tanh_mufu(cd);
                ctA = cd; cbA = cbnA; oA = oG;
                s_h[0][ch] = befA;
            }
            BAR_ARRIVE(2);              // h_A released to producers
            if (aA) {
                const int base = (bA * LP1 + l + 1) * HID + ch;
                g_state [base] = make_float4(cA, cbnA, oA, decA);
                g_before[base] = befA;
            }

            // own GEMM-B column (overlaps producer GEMM-B / next GEMM-A)
            const float accB = col_dot(s_h[1], w2, w0, bj, s_dt[1][l]);
            const float decB = fsoftplus(accB);
            const float eB   = ex2f(-decB * s_dt[1][l + 1] * LOG2E);

            BAR_SYNC(3);                // wait gates B
            float cB = 0.f, cbnB = 0.f, oB = 0.f, befB = 0.f;
            if (aB) {
                const float iG = s_v[1][ch],        fG = s_v[1][ 64 + ch];
                const float zG = s_v[1][128 + ch],  oG = s_v[1][192 + ch];
                const float ib = s_v[1][256 + ch],  fb = s_v[1][320 + ch];
                cB   = fmaf(fG, ctB, iG * zG);
                cbnB = fmaf(fb, cbB, ib * zG);
                const float cd = fmaf(cB - cbnB, eB, cbnB);
                befB = oG * tanh_mufu(cd);
                ctB = cd; cbB = cbnB; oB = oG;
                s_h[1][ch] = befB;
            }
            BAR_ARRIVE(4);              // h_B released to producers
            if (aB) {
                const int base = (bB * LP1 + l + 1) * HID + ch;
                g_state [base] = make_float4(cB, cbnB, oB, decB);
                g_before[base] = befB;
            }
        }
    }
}

// --------------------- Kernel 2: MC integral + log-intensity -----------------
// Warp per (b,l); lane = MC sample (30 active). Per-channel params pre-
// transformed into shared {m, A, cbar, o*wf}; inner loop is LDS-broadcast +
// 2 MUFU + 3 FMA per channel with zero shuffles.
__global__ void __launch_bounds__(256, 8)
mc_kernel(const float* __restrict__ Wf,    // [64]
          const float* __restrict__ bf,    // [1]
          const int*   __restrict__ lens)  // [B]
{
    __shared__ __align__(16) float4 s_st[8][HID];

    const int warp = threadIdx.x >> 5;
    const int wid  = blockIdx.x * 8 + warp;
    if (wid >= TOTAL) return;
    const int lane = threadIdx.x & 31;
    const int b = wid / LP1;
    const int l = wid - b * LP1;
    const int len = lens[b];

    float out = 0.0f;
    if (l <= len) {
        const float dtl = g_dt[wid];
        const float bfv = bf[0];
        const int base = wid * HID;
        const float wf0 = Wf[lane], wf1 = Wf[lane + 32];

        // stage transformed per-channel params + event-term partial dot
        const float4 s0 = g_state[base + lane];
        const float4 s1 = g_state[base + lane + 32];
        const float mscale = -dtl * LOG2E;
        s_st[warp][lane]      = make_float4(s0.w * mscale, s0.x - s0.y, s0.y, s0.z * wf0);
        s_st[warp][lane + 32] = make_float4(s1.w * mscale, s1.x - s1.y, s1.y, s1.z * wf1);

        float q = 0.0f;
        if (l < len)
            q = fmaf(g_before[base + lane], wf0, g_before[base + lane + 32] * wf1);
        __syncwarp();

        // lane s: full 64-channel intensity at random time u_s * dt
        float sp = 0.0f;
        if (lane < NMC) {
            const float u = tf_uniform((uint32_t)lane * (uint32_t)TOTAL + (uint32_t)wid);
            float acc0 = 0.0f, acc1 = 0.0f;
            const float4* st = s_st[warp];
#pragma unroll 8
            for (int ch = 0; ch < HID; ch += 2) {
                const float4 t0 = st[ch], t1 = st[ch + 1];
                acc0 = fmaf(t0.w, tanh_mufu(fmaf(t0.y, ex2f(u * t0.x), t0.z)), acc0);
                acc1 = fmaf(t1.w, tanh_mufu(fmaf(t1.y, ex2f(u * t1.x), t1.z)), acc1);
            }
            sp = fsoftplus(acc0 + acc1 + bfv);
        }
        // sum softplus over 30 samples + event-term dot, one reduction pass
#pragma unroll
        for (int off = 16; off; off >>= 1) {
            sp += __shfl_xor_sync(0xFFFFFFFFu, sp, off);
            q  += __shfl_xor_sync(0xFFFFFFFFu, q,  off);
        }
        const float lamb_int = (sp * (1.0f / NMC) + EPS_L) * dtl;
        float ev = 0.0f;
        if (l < len) ev = flog(fsoftplus(q + bfv) + EPS_L);
        out = ev - lamb_int;
    }
    if (lane == 0) g_part[wid] = out;
}

// --------------------------- Kernel 3: reduction -----------------------------
__global__ void __launch_bounds__(1024, 1)
reduce_kernel(float* __restrict__ out)
{
    __shared__ float sh[1024];
    const int t = threadIdx.x;
    float s = 0.0f;
    for (int i = t; i < TOTAL; i += 1024) s += g_part[i];
    sh[t] = s;
    __syncthreads();
#pragma unroll
    for (int ofs = 512; ofs; ofs >>= 1) {
        if (t < ofs) sh[t] += sh[t + ofs];
        __syncthreads();
    }
    if (t == 0) out[0] = -sh[0] * (1.0f / BATCH);
}

// ------------------------------- launcher ------------------------------------
extern "C" void kernel_launch(void* const* d_in, const int* in_sizes, int n_in,
                              void* d_out, int out_size)
{
    const float* seq  = nullptr;
    const float* Wrec = nullptr;
    const float* brec = nullptr;
    const float* Wf   = nullptr;
    const float* bf   = nullptr;
    const int*   lens = nullptr;
    for (int i = 0; i < n_in; i++) {
        const int s = in_sizes[i];
        if      (s == BATCH * MAXL)     seq  = (const float*)d_in[i];
        else if (s == 65 * SEVENH)      Wrec = (const float*)d_in[i];
        else if (s == SEVENH)           brec = (const float*)d_in[i];
        else if (s == 1)                bf   = (const float*)d_in[i];
        else if (s == HID) {
            if (!Wf) Wf = (const float*)d_in[i];
            else     lens = (const int*)d_in[i];
        }
    }

    scan_kernel<<<BATCH / 2, SEVENH>>>(seq, Wrec, brec, lens);
    mc_kernel<<<(TOTAL + 7) / 8, 256>>>(Wf, bf, lens);
    reduce_kernel<<<1, 1024>>>((float*)d_out);
}

// round 6
// speedup vs baseline: 1.3975x; 1.3975x over previous
#include <cuda_runtime.h>
#include <cstdint>

// ---------------------------------------------------------------------------
// LSTM Neural Hawkes Process NLL  (B=64, L=1024, H=64)
// R6: ONE barrier per step. Gates published (ping-pong buffer), then every
// warp replicates the 64-channel epilogue into its own private h buffer
// (carries replicated in registers; gate-6 threads pre-publish e=exp(-dec*dt)
// so replication costs only 2 tanh/lane). Warp 12 does global stores, async.
// ---------------------------------------------------------------------------

#define BATCH   64
#define MAXL    1024
#define LP1     1025
#define HID     64
#define SEVENH  448
#define NWARP   14
#define NMC     30
#define T_END   100.0f
#define EPS_L   1e-10f
#define TOTAL   (BATCH * LP1)          // 65600
#define LOG2E   1.4426950408889634f
#define LN2     0.6931471805599453f

// ------------------------- device scratch (no mallocs) ---------------------
__device__ float4 g_state [TOTAL * HID];   // {c, cbar, o, dec}
__device__ float  g_before[TOTAL * HID];
__device__ float  g_dt    [TOTAL];
__device__ float  g_part  [TOTAL];

// ------------------------------ fast math -----------------------------------
__device__ __forceinline__ float ex2f(float x){ float y; asm("ex2.approx.f32 %0,%1;":"=f"(y):"f"(x)); return y; }
__device__ __forceinline__ float lg2f(float x){ float y; asm("lg2.approx.f32 %0,%1;":"=f"(y):"f"(x)); return y; }
__device__ __forceinline__ float tanh_mufu(float x){ float y; asm("tanh.approx.f32 %0,%1;":"=f"(y):"f"(x)); return y; }
__device__ __forceinline__ float fsig(float x){ return fmaf(0.5f, tanh_mufu(0.5f * x), 0.5f); }
__device__ __forceinline__ float fsoftplus(float x){
    return fmaxf(x, 0.0f) + LN2 * lg2f(1.0f + ex2f(-fabsf(x) * LOG2E));
}
__device__ __forceinline__ float flog(float x){ return LN2 * lg2f(x); }

// ------------------------------ packed f32x2 --------------------------------
__device__ __forceinline__ void fma2(unsigned long long& d, unsigned long long a, unsigned long long b){
    asm("fma.rn.f32x2 %0, %1, %2, %0;" : "+l"(d) : "l"(a), "l"(b));
}
__device__ __forceinline__ void add2(unsigned long long& d, unsigned long long a){
    asm("add.rn.f32x2 %0, %1, %0;" : "+l"(d) : "l"(a));
}
__device__ __forceinline__ unsigned long long pack2(float lo, float hi){
    unsigned long long r; asm("mov.b64 %0, {%1,%2};" : "=l"(r) : "f"(lo), "f"(hi)); return r;
}
__device__ __forceinline__ float2 unpack2(unsigned long long v){
    float2 r; asm("mov.b64 {%0,%1}, %2;" : "=f"(r.x), "=f"(r.y) : "l"(v)); return r;
}

// ------------------------------ Threefry-2x32-20 ----------------------------
__device__ __forceinline__ uint32_t rotl32(uint32_t x, int r){ return (x << r) | (x >> (32 - r)); }
__device__ __forceinline__ float tf_uniform(uint32_t flat){
    // JAX partitionable threefry, key (0,42): bits = out0 ^ out1
    uint32_t k0 = 0u, k1 = 42u, ks2 = k0 ^ k1 ^ 0x1BD11BDAu;
    uint32_t x0 = 0u + k0, x1 = flat + k1;
#define TF_R(r) { x0 += x1; x1 = rotl32(x1, (r)); x1 ^= x0; }
    TF_R(13) TF_R(15) TF_R(26) TF_R(6)   x0 += k1;  x1 += ks2 + 1u;
    TF_R(17) TF_R(29) TF_R(16) TF_R(24)  x0 += ks2; x1 += k0  + 2u;
    TF_R(13) TF_R(15) TF_R(26) TF_R(6)   x0 += k0;  x1 += k1  + 3u;
    TF_R(17) TF_R(29) TF_R(16) TF_R(24)  x0 += k1;  x1 += ks2 + 4u;
    TF_R(13) TF_R(15) TF_R(26) TF_R(6)   x0 += ks2; x1 += k0  + 5u;
#undef TF_R
    uint32_t bits = x0 ^ x1;
    return __uint_as_float((bits >> 9) | 0x3F800000u) - 1.0f;
}

// ------------------------------ Kernel 1: scan -------------------------------
// One CTA per batch, 448 threads (thread j = GEMM column j). h lives in 14
// per-warp private buffers; after the single per-step barrier every warp
// reconstructs h itself (no cross-warp consumer stage).
__global__ void __launch_bounds__(SEVENH, 1)
scan_kernel(const float* __restrict__ seq,    // [B, L, 1]
            const float* __restrict__ Wrec,   // [65, 448]
            const float* __restrict__ brec,   // [448]
            const int*   __restrict__ lens)   // [B]
{
    __shared__ __align__(16) float s_hw[NWARP][HID];  // per-warp h buffers
    __shared__ float s_v[2][512];                     // ping-pong: 0..383 gates,
                                                      // 384+ch = e, 448+ch = dec
    __shared__ float s_dt[LP1];

    const int b    = blockIdx.x;
    const int j    = threadIdx.x;
    const int w    = j >> 5;
    const int lane = j & 31;
    const int len  = lens[b];
    const float* sp = seq + b * MAXL;

    for (int l = j; l <= MAXL; l += SEVENH) {
        float v;
        if (l < len)        v = (l == 0) ? sp[0] : sp[l] - sp[l - 1];
        else if (l == len)  v = T_END - sp[len - 1];
        else                v = -1.0f;
        s_dt[l] = v;
        g_dt[b * LP1 + l] = v;
    }

    // zero own warp's h buffer; warps 12/13 threads also zero state index 0
    s_hw[w][lane]      = 0.0f;
    s_hw[w][lane + 32] = 0.0f;
    if (j >= 384) {
        const int ch = j - 384;
        g_state [(b * LP1) * HID + ch] = make_float4(0.f, 0.f, 0.f, 0.f);
        g_before[(b * LP1) * HID + ch] = 0.0f;
    }

    // column weights: row 0 (x) scalar + 32 packed f32x2 pairs for h rows
    const float w0 = Wrec[j];
    const float bj = brec[j];
    unsigned long long w2[32];
#pragma unroll
    for (int k = 0; k < 32; k++)
        w2[k] = pack2(Wrec[(2*k + 1) * SEVENH + j], Wrec[(2*k + 2) * SEVENH + j]);

    const int gate = j >> 6;            // 0:i 1:f 2:z 3:o 4:ib 5:fb 6:d
    const int chj  = j & 63;            // channel for gate-6 threads
    // replicated per-warp carries for channels (lane, lane+32)
    float ct0 = 0.0f, cb0 = 0.0f, ct1 = 0.0f, cb1 = 0.0f;
    __syncthreads();

    for (int l = 0; l < len; l++) {
        const int   p  = l & 1;
        const float dt = s_dt[l];

        // ---- phase 1: column GEMM against OWN warp's h buffer (f32x2)
        unsigned long long a0 = 0ull, a1 = 0ull, a2 = 0ull, a3 = 0ull;
        const ulonglong2* h2 = reinterpret_cast<const ulonglong2*>(s_hw[w]);
#pragma unroll
        for (int q = 0; q < 4; q++) {
            ulonglong2 u = h2[2*q], v = h2[2*q + 1];
            fma2(a0, w2[4*q + 0],  u.x);
            fma2(a1, w2[4*q + 1],  u.y);
            fma2(a2, w2[4*q + 2],  v.x);
            fma2(a3, w2[4*q + 3],  v.y);
            ulonglong2 s = h2[2*q + 8], t = h2[2*q + 9];
            fma2(a0, w2[4*q + 16], s.x);
            fma2(a1, w2[4*q + 17], s.y);
            fma2(a2, w2[4*q + 18], t.x);
            fma2(a3, w2[4*q + 19], t.y);
        }
        add2(a0, a1); add2(a2, a3); add2(a0, a2);
        float2 rr = unpack2(a0);
        const float acc = (rr.x + rr.y) + fmaf(w0, dt, bj);

        // nonlinearity + publish (gate 6 publishes e AND dec)
        if (gate == 6) {
            const float dec = fsoftplus(acc);
            s_v[p][384 + chj] = ex2f(-dec * s_dt[l + 1] * LOG2E);
            s_v[p][448 + chj] = dec;
        } else if (gate == 2) {
            s_v[p][j] = tanh_mufu(acc);
        } else {
            s_v[p][j] = fsig(acc);
        }
        __syncthreads();                 // the ONLY barrier per step

        // ---- phase 2: every warp reconstructs all 64 h channels itself
        const float* sv = s_v[p];
        const int ch0 = lane, ch1 = lane + 32;
        const float i0 = sv[ch0],        f0 = sv[ 64 + ch0];
        const float z0 = sv[128 + ch0],  o0 = sv[192 + ch0];
        const float q0 = sv[256 + ch0],  g0 = sv[320 + ch0];
        const float e0 = sv[384 + ch0];
        const float i1 = sv[ch1],        f1 = sv[ 64 + ch1];
        const float z1 = sv[128 + ch1],  o1 = sv[192 + ch1];
        const float q1 = sv[256 + ch1],  g1 = sv[320 + ch1];
        const float e1 = sv[384 + ch1];

        const float c0n  = fmaf(f0, ct0, i0 * z0);
        const float cb0n = fmaf(g0, cb0, q0 * z0);
        const float cd0  = fmaf(c0n - cb0n, e0, cb0n);
        const float bef0 = o0 * tanh_mufu(cd0);
        const float c1n  = fmaf(f1, ct1, i1 * z1);
        const float cb1n = fmaf(g1, cb1, q1 * z1);
        const float cd1  = fmaf(c1n - cb1n, e1, cb1n);
        const float bef1 = o1 * tanh_mufu(cd1);
        ct0 = cd0; cb0 = cb0n; ct1 = cd1; cb1 = cb1n;
        s_hw[w][ch0] = bef0;
        s_hw[w][ch1] = bef1;
        __syncwarp();

        // warp 12 persists state for all 64 channels (nobody waits on this)
        if (w == 12) {
            const int base = (b * LP1 + l + 1) * HID;
            g_state [base + ch0] = make_float4(c0n, cb0n, o0, sv[448 + ch0]);
            g_state [base + ch1] = make_float4(c1n, cb1n, o1, sv[448 + ch1]);
            g_before[base + ch0] = bef0;
            g_before[base + ch1] = bef1;
        }
    }
}

// --------------------- Kernel 2: MC integral + log-intensity -----------------
// Warp per (b,l); lane = MC sample (30 active). Per-channel params pre-
// transformed into shared {m, A, cbar, o*wf}; inner loop is LDS-broadcast +
// 2 MUFU + 3 FMA per channel with zero shuffles.
__global__ void __launch_bounds__(256, 8)
mc_kernel(const float* __restrict__ Wf,    // [64]
          const float* __restrict__ bf,    // [1]
          const int*   __restrict__ lens)  // [B]
{
    __shared__ __align__(16) float4 s_st[8][HID];

    const int warp = threadIdx.x >> 5;
    const int wid  = blockIdx.x * 8 + warp;
    if (wid >= TOTAL) return;
    const int lane = threadIdx.x & 31;
    const int b = wid / LP1;
    const int l = wid - b * LP1;
    const int len = lens[b];

    float out = 0.0f;
    if (l <= len) {
        const float dtl = g_dt[wid];
        const float bfv = bf[0];
        const int base = wid * HID;
        const float wf0 = Wf[lane], wf1 = Wf[lane + 32];

        // stage transformed per-channel params + event-term partial dot
        const float4 s0 = g_state[base + lane];
        const float4 s1 = g_state[base + lane + 32];
        const float mscale = -dtl * LOG2E;
        s_st[warp][lane]      = make_float4(s0.w * mscale, s0.x - s0.y, s0.y, s0.z * wf0);
        s_st[warp][lane + 32] = make_float4(s1.w * mscale, s1.x - s1.y, s1.y, s1.z * wf1);

        float q = 0.0f;
        if (l < len)
            q = fmaf(g_before[base + lane], wf0, g_before[base + lane + 32] * wf1);
        __syncwarp();

        // lane s: full 64-channel intensity at random time u_s * dt
        float sp = 0.0f;
        if (lane < NMC) {
            const float u = tf_uniform((uint32_t)lane * (uint32_t)TOTAL + (uint32_t)wid);
            float acc0 = 0.0f, acc1 = 0.0f;
            const float4* st = s_st[warp];
#pragma unroll 8
            for (int ch = 0; ch < HID; ch += 2) {
                const float4 t0 = st[ch], t1 = st[ch + 1];
                acc0 = fmaf(t0.w, tanh_mufu(fmaf(t0.y, ex2f(u * t0.x), t0.z)), acc0);
                acc1 = fmaf(t1.w, tanh_mufu(fmaf(t1.y, ex2f(u * t1.x), t1.z)), acc1);
            }
            sp = fsoftplus(acc0 + acc1 + bfv);
        }
        // sum softplus over 30 samples + event-term dot, one reduction pass
#pragma unroll
        for (int off = 16; off; off >>= 1) {
            sp += __shfl_xor_sync(0xFFFFFFFFu, sp, off);
            q  += __shfl_xor_sync(0xFFFFFFFFu, q,  off);
        }
        const float lamb_int = (sp * (1.0f / NMC) + EPS_L) * dtl;
        float ev = 0.0f;
        if (l < len) ev = flog(fsoftplus(q + bfv) + EPS_L);
        out = ev - lamb_int;
    }
    if (lane == 0) g_part[wid] = out;
}

// --------------------------- Kernel 3: reduction -----------------------------
__global__ void __launch_bounds__(1024, 1)
reduce_kernel(float* __restrict__ out)
{
    __shared__ float sh[1024];
    const int t = threadIdx.x;
    float s = 0.0f;
    for (int i = t; i < TOTAL; i += 1024) s += g_part[i];
    sh[t] = s;
    __syncthreads();
#pragma unroll
    for (int ofs = 512; ofs; ofs >>= 1) {
        if (t < ofs) sh[t] += sh[t + ofs];
        __syncthreads();
    }
    if (t == 0) out[0] = -sh[0] * (1.0f / BATCH);
}

// ------------------------------- launcher ------------------------------------
extern "C" void kernel_launch(void* const* d_in, const int* in_sizes, int n_in,
                              void* d_out, int out_size)
{
    const float* seq  = nullptr;
    const float* Wrec = nullptr;
    const float* brec = nullptr;
    const float* Wf   = nullptr;
    const float* bf   = nullptr;
    const int*   lens = nullptr;
    for (int i = 0; i < n_in; i++) {
        const int s = in_sizes[i];
        if      (s == BATCH * MAXL)     seq  = (const float*)d_in[i];
        else if (s == 65 * SEVENH)      Wrec = (const float*)d_in[i];
        else if (s == SEVENH)           brec = (const float*)d_in[i];
        else if (s == 1)                bf   = (const float*)d_in[i];
        else if (s == HID) {
            if (!Wf) Wf = (const float*)d_in[i];
            else     lens = (const int*)d_in[i];
        }
    }

    scan_kernel<<<BATCH, SEVENH>>>(seq, Wrec, brec, lens);
    mc_kernel<<<(TOTAL + 7) / 8, 256>>>(Wf, bf, lens);
    reduce_kernel<<<1, 1024>>>((float*)d_out);
}